// round 2
// baseline (speedup 1.0000x reference)
#include <cuda_runtime.h>
#include <cuda_bf16.h>

#define EMBED_DIM 256
#define NUM_EDGES 16384

// One CTA per hyperedge. segment_ids is sorted, so the members of edge e are a
// contiguous run [lo, hi) found by binary search. Thread t accumulates column t.
// NOTE: JAX default config disables x64, so the "int64" inputs are int32.
__global__ void __launch_bounds__(EMBED_DIM)
hyperedge_agg_kernel(const float* __restrict__ emb,   // [NUM_NODES, 256]
                     const int* __restrict__ nidx,    // [TOTAL]
                     const int* __restrict__ seg,     // [TOTAL] sorted
                     float* __restrict__ out,         // [NUM_EDGES, 256]
                     int total)
{
    const int e = blockIdx.x;
    __shared__ int s_lo, s_hi;

    if (threadIdx.x == 0) {
        // lower_bound(seg, e)
        int lo = 0, hi = total;
        while (lo < hi) {
            int mid = (lo + hi) >> 1;
            if (seg[mid] < e) lo = mid + 1; else hi = mid;
        }
        s_lo = lo;
        // upper_bound(seg, e)
        hi = total;
        while (lo < hi) {
            int mid = (lo + hi) >> 1;
            if (seg[mid] <= e) lo = mid + 1; else hi = mid;
        }
        s_hi = lo;
    }
    __syncthreads();

    const int lo = s_lo;
    const int hi = s_hi;
    const int t  = threadIdx.x;

    float acc = 0.0f;

    // Unroll by 4 to expose memory-level parallelism: 4 independent row reads
    // in flight per thread.
    int m = lo;
    for (; m + 4 <= hi; m += 4) {
        int n0 = nidx[m + 0];
        int n1 = nidx[m + 1];
        int n2 = nidx[m + 2];
        int n3 = nidx[m + 3];
        float v0 = emb[(long long)n0 * EMBED_DIM + t];
        float v1 = emb[(long long)n1 * EMBED_DIM + t];
        float v2 = emb[(long long)n2 * EMBED_DIM + t];
        float v3 = emb[(long long)n3 * EMBED_DIM + t];
        acc += v0 + v1 + v2 + v3;
    }
    for (; m < hi; m++) {
        int n = nidx[m];
        acc += emb[(long long)n * EMBED_DIM + t];
    }

    int cnt = hi - lo;
    float inv = 1.0f / (float)(cnt > 0 ? cnt : 1);
    out[(long long)e * EMBED_DIM + t] = acc * inv;
}

extern "C" void kernel_launch(void* const* d_in, const int* in_sizes, int n_in,
                              void* d_out, int out_size)
{
    const float* emb  = (const float*)d_in[0];
    const int*   nidx = (const int*)d_in[1];
    const int*   seg  = (const int*)d_in[2];
    float*       out  = (float*)d_out;
    const int total = in_sizes[1];

    hyperedge_agg_kernel<<<NUM_EDGES, EMBED_DIM>>>(emb, nidx, seg, out, total);
}

// round 3
// speedup vs baseline: 2.7250x; 2.7250x over previous
#include <cuda_runtime.h>
#include <cuda_bf16.h>

#define EMBED_DIM 256
#define NUM_EDGES 16384
#define CHUNK     512
#define NTHREADS  256

// Precomputed segment boundaries: g_offs[e] = lower_bound(seg, e), g_offs[NUM_EDGES] = total.
__device__ int g_offs[NUM_EDGES + 1];

__global__ void bounds_kernel(const int* __restrict__ seg, int total)
{
    int e = blockIdx.x * blockDim.x + threadIdx.x;
    if (e > NUM_EDGES) return;
    if (e == NUM_EDGES) { g_offs[e] = total; return; }
    int lo = 0, hi = total;
    while (lo < hi) {
        int mid = (lo + hi) >> 1;
        if (seg[mid] < e) lo = mid + 1; else hi = mid;
    }
    g_offs[e] = lo;
}

__device__ __forceinline__ void acc4(float4& a, const float4 v)
{
    a.x += v.x; a.y += v.y; a.z += v.z; a.w += v.w;
}

// One CTA per hyperedge. 256 threads = 64 float4-columns x 4 member-slices.
// Indices staged in shared; each slice keeps 4 independent float4 gathers in flight.
__global__ void __launch_bounds__(NTHREADS)
agg_kernel(const float* __restrict__ emb,   // [NUM_NODES, 256]
           const int*   __restrict__ nidx,  // [TOTAL]
           float*       __restrict__ out)   // [NUM_EDGES, 256]
{
    __shared__ int    s_idx[CHUNK];
    __shared__ float4 s_red[NTHREADS];

    const int e   = blockIdx.x;
    const int tid = threadIdx.x;
    const int c   = tid & 63;   // float4 column 0..63
    const int r   = tid >> 6;   // member slice 0..3

    const int lo = g_offs[e];
    const int hi = g_offs[e + 1];

    const float4* __restrict__ rows = (const float4*)emb;  // row n = rows[n*64 + c]

    float4 acc = make_float4(0.f, 0.f, 0.f, 0.f);

    for (int base = lo; base < hi; base += CHUNK) {
        const int n = min(CHUNK, hi - base);
        if (base != lo) __syncthreads();           // protect s_idx reuse
        for (int i = tid; i < n; i += NTHREADS)
            s_idx[i] = nidx[base + i];
        __syncthreads();

        int m = r;
        // 4 independent float4 gathers per iteration (members m, m+4, m+8, m+12 for this slice)
        for (; m + 12 < n; m += 16) {
            const int n0 = s_idx[m];
            const int n1 = s_idx[m + 4];
            const int n2 = s_idx[m + 8];
            const int n3 = s_idx[m + 12];
            float4 v0 = rows[(size_t)n0 * 64 + c];
            float4 v1 = rows[(size_t)n1 * 64 + c];
            float4 v2 = rows[(size_t)n2 * 64 + c];
            float4 v3 = rows[(size_t)n3 * 64 + c];
            acc4(acc, v0); acc4(acc, v1); acc4(acc, v2); acc4(acc, v3);
        }
        for (; m < n; m += 4)
            acc4(acc, rows[(size_t)s_idx[m] * 64 + c]);
    }

    // Reduce the 4 slices.
    s_red[tid] = acc;
    __syncthreads();
    if (tid < 64) {
        float4 a = s_red[tid];
        float4 b = s_red[tid + 64];
        float4 d = s_red[tid + 128];
        float4 f = s_red[tid + 192];
        a.x += b.x + d.x + f.x;
        a.y += b.y + d.y + f.y;
        a.z += b.z + d.z + f.z;
        a.w += b.w + d.w + f.w;

        const int cnt = hi - lo;
        const float inv = 1.0f / (float)(cnt > 0 ? cnt : 1);
        a.x *= inv; a.y *= inv; a.z *= inv; a.w *= inv;
        ((float4*)out)[(size_t)e * 64 + tid] = a;
    }
}

extern "C" void kernel_launch(void* const* d_in, const int* in_sizes, int n_in,
                              void* d_out, int out_size)
{
    const float* emb  = (const float*)d_in[0];
    const int*   nidx = (const int*)d_in[1];
    const int*   seg  = (const int*)d_in[2];
    float*       out  = (float*)d_out;
    const int total = in_sizes[1];

    bounds_kernel<<<(NUM_EDGES + 1 + 255) / 256, 256>>>(seg, total);
    agg_kernel<<<NUM_EDGES, NTHREADS>>>(emb, nidx, out);
}

// round 4
// speedup vs baseline: 3.4756x; 1.2754x over previous
#include <cuda_runtime.h>
#include <cuda_bf16.h>

#define EMBED_DIM   256
#define NUM_EDGES   16384
#define NTHREADS    256
#define WARPS_CTA   (NTHREADS / 32)

// g_offs[e] = lower_bound(seg, e); g_offs[NUM_EDGES] = total.
__device__ int g_offs[NUM_EDGES + 1];

// Diff-based boundary fill: no dependent load chains.
__global__ void bounds_kernel(const int* __restrict__ seg, int total)
{
    int i = blockIdx.x * blockDim.x + threadIdx.x;
    if (i >= total) return;
    int cur = seg[i];
    if (i == 0) {
        for (int e = 0; e <= cur; e++) g_offs[e] = 0;
    } else {
        int prev = seg[i - 1];
        for (int e = prev + 1; e <= cur; e++) g_offs[e] = i;
    }
    if (i == total - 1) {
        for (int e = cur + 1; e <= NUM_EDGES; e++) g_offs[e] = total;
    }
}

__device__ __forceinline__ void acc4(float4& a, const float4 v)
{
    a.x += v.x; a.y += v.y; a.z += v.z; a.w += v.w;
}

// One WARP per hyperedge. Lane l owns float4 columns l and l+32 (full 256-float
// row per warp). No shared memory, no block barriers, no reduction.
__global__ void __launch_bounds__(NTHREADS)
agg_kernel(const float* __restrict__ emb,   // [NUM_NODES, 256]
           const int*   __restrict__ nidx,  // [TOTAL]
           float*       __restrict__ out)   // [NUM_EDGES, 256]
{
    const int lane = threadIdx.x & 31;
    const int e    = blockIdx.x * WARPS_CTA + (threadIdx.x >> 5);

    const int lo = g_offs[e];
    const int hi = g_offs[e + 1];

    const float4* __restrict__ rows = (const float4*)emb;

    float4 a0 = make_float4(0.f, 0.f, 0.f, 0.f);
    float4 a1 = make_float4(0.f, 0.f, 0.f, 0.f);

    for (int base = lo; base < hi; base += 32) {
        const int cnt = min(32, hi - base);
        // Coalesced index load, one member per lane.
        int myidx = (lane < cnt) ? nidx[base + lane] : 0;

        int j = 0;
        // 4 members per iteration -> 8 independent float4 gathers in flight.
        for (; j + 3 < cnt; j += 4) {
            const int n0 = __shfl_sync(0xffffffffu, myidx, j);
            const int n1 = __shfl_sync(0xffffffffu, myidx, j + 1);
            const int n2 = __shfl_sync(0xffffffffu, myidx, j + 2);
            const int n3 = __shfl_sync(0xffffffffu, myidx, j + 3);
            float4 v00 = rows[(size_t)n0 * 64 + lane];
            float4 v01 = rows[(size_t)n0 * 64 + lane + 32];
            float4 v10 = rows[(size_t)n1 * 64 + lane];
            float4 v11 = rows[(size_t)n1 * 64 + lane + 32];
            float4 v20 = rows[(size_t)n2 * 64 + lane];
            float4 v21 = rows[(size_t)n2 * 64 + lane + 32];
            float4 v30 = rows[(size_t)n3 * 64 + lane];
            float4 v31 = rows[(size_t)n3 * 64 + lane + 32];
            acc4(a0, v00); acc4(a1, v01);
            acc4(a0, v10); acc4(a1, v11);
            acc4(a0, v20); acc4(a1, v21);
            acc4(a0, v30); acc4(a1, v31);
        }
        for (; j < cnt; j++) {
            const int n = __shfl_sync(0xffffffffu, myidx, j);
            acc4(a0, rows[(size_t)n * 64 + lane]);
            acc4(a1, rows[(size_t)n * 64 + lane + 32]);
        }
    }

    const int cnt = hi - lo;
    const float inv = 1.0f / (float)(cnt > 0 ? cnt : 1);
    a0.x *= inv; a0.y *= inv; a0.z *= inv; a0.w *= inv;
    a1.x *= inv; a1.y *= inv; a1.z *= inv; a1.w *= inv;

    float4* o = (float4*)out + (size_t)e * 64;
    o[lane]      = a0;
    o[lane + 32] = a1;
}

extern "C" void kernel_launch(void* const* d_in, const int* in_sizes, int n_in,
                              void* d_out, int out_size)
{
    const float* emb  = (const float*)d_in[0];
    const int*   nidx = (const int*)d_in[1];
    const int*   seg  = (const int*)d_in[2];
    float*       out  = (float*)d_out;
    const int total = in_sizes[1];

    bounds_kernel<<<(total + 255) / 256, 256>>>(seg, total);
    agg_kernel<<<NUM_EDGES / WARPS_CTA, NTHREADS>>>(emb, nidx, out);
}

// round 6
// speedup vs baseline: 3.6001x; 1.0358x over previous
#include <cuda_runtime.h>
#include <cuda_bf16.h>

#define EMBED_DIM   256
#define NUM_EDGES   16384
#define NTHREADS    256
#define WARPS_CTA   (NTHREADS / 32)

// g_offs[e] = lower_bound(seg, e); g_offs[NUM_EDGES] = total.
__device__ int g_offs[NUM_EDGES + 1];

// Diff-based boundary fill: no dependent load chains.
__global__ void bounds_kernel(const int* __restrict__ seg, int total)
{
    int i = blockIdx.x * blockDim.x + threadIdx.x;
    if (i >= total) return;
    int cur = seg[i];
    if (i == 0) {
        for (int e = 0; e <= cur; e++) g_offs[e] = 0;
    } else {
        int prev = seg[i - 1];
        for (int e = prev + 1; e <= cur; e++) g_offs[e] = i;
    }
    if (i == total - 1) {
        for (int e = cur + 1; e <= NUM_EDGES; e++) g_offs[e] = total;
    }
}

// 32-byte (8-float) gather with L2 evict_last (ptxas requires .v4.b64 for this hint).
__device__ __forceinline__ ulonglong4 ldg_el8(const ulonglong4* p)
{
    ulonglong4 v;
    asm volatile("ld.global.nc.L2::evict_last.v4.b64 {%0,%1,%2,%3}, [%4];"
                 : "=l"(v.x), "=l"(v.y), "=l"(v.z), "=l"(v.w)
                 : "l"(p));
    return v;
}

// Streaming index load (evict-first).
__device__ __forceinline__ int ldg_cs(const int* p)
{
    int v;
    asm volatile("ld.global.cs.b32 %0, [%1];" : "=r"(v) : "l"(p));
    return v;
}

// Streaming 32-byte store (evict-first: don't displace table lines in L2).
__device__ __forceinline__ void stg_cs8(ulonglong4* p, const ulonglong4 v)
{
    asm volatile("st.global.cs.v4.b64 [%0], {%1,%2,%3,%4};"
                 :: "l"(p), "l"(v.x), "l"(v.y), "l"(v.z), "l"(v.w));
}

__device__ __forceinline__ void accadd8(float* a, const ulonglong4 v)
{
    const float* f = (const float*)&v;
#pragma unroll
    for (int i = 0; i < 8; i++) a[i] += f[i];
}

// One WARP per hyperedge. Lane l owns the 32-byte chunk at byte offset 32*l of
// the 1024-byte row: one 256-bit load covers the whole row per member per warp.
__global__ void __launch_bounds__(NTHREADS)
agg_kernel(const float* __restrict__ emb,   // [NUM_NODES, 256]
           const int*   __restrict__ nidx,  // [TOTAL]
           float*       __restrict__ out)   // [NUM_EDGES, 256]
{
    const int lane = threadIdx.x & 31;
    const int e    = blockIdx.x * WARPS_CTA + (threadIdx.x >> 5);

    const int lo = g_offs[e];
    const int hi = g_offs[e + 1];

    const ulonglong4* __restrict__ rows = (const ulonglong4*)emb;  // 32 chunks/row

    float acc[8];
#pragma unroll
    for (int i = 0; i < 8; i++) acc[i] = 0.0f;

    for (int base = lo; base < hi; base += 32) {
        const int cnt = min(32, hi - base);
        // Coalesced index load, one member per lane.
        int myidx = (lane < cnt) ? ldg_cs(nidx + base + lane) : 0;

        int j = 0;
        // 4 members per iteration -> 4 independent 32B gathers in flight per thread.
        for (; j + 3 < cnt; j += 4) {
            const int n0 = __shfl_sync(0xffffffffu, myidx, j);
            const int n1 = __shfl_sync(0xffffffffu, myidx, j + 1);
            const int n2 = __shfl_sync(0xffffffffu, myidx, j + 2);
            const int n3 = __shfl_sync(0xffffffffu, myidx, j + 3);
            ulonglong4 v0 = ldg_el8(rows + (size_t)n0 * 32 + lane);
            ulonglong4 v1 = ldg_el8(rows + (size_t)n1 * 32 + lane);
            ulonglong4 v2 = ldg_el8(rows + (size_t)n2 * 32 + lane);
            ulonglong4 v3 = ldg_el8(rows + (size_t)n3 * 32 + lane);
            accadd8(acc, v0);
            accadd8(acc, v1);
            accadd8(acc, v2);
            accadd8(acc, v3);
        }
        for (; j < cnt; j++) {
            const int n = __shfl_sync(0xffffffffu, myidx, j);
            accadd8(acc, ldg_el8(rows + (size_t)n * 32 + lane));
        }
    }

    const int cnt = hi - lo;
    const float inv = 1.0f / (float)(cnt > 0 ? cnt : 1);
#pragma unroll
    for (int i = 0; i < 8; i++) acc[i] *= inv;

    ulonglong4 res;
    float* rf = (float*)&res;
#pragma unroll
    for (int i = 0; i < 8; i++) rf[i] = acc[i];

    stg_cs8((ulonglong4*)out + (size_t)e * 32 + lane, res);
}

extern "C" void kernel_launch(void* const* d_in, const int* in_sizes, int n_in,
                              void* d_out, int out_size)
{
    const float* emb  = (const float*)d_in[0];
    const int*   nidx = (const int*)d_in[1];
    const int*   seg  = (const int*)d_in[2];
    float*       out  = (float*)d_out;
    const int total = in_sizes[1];

    bounds_kernel<<<(total + 255) / 256, 256>>>(seg, total);
    agg_kernel<<<NUM_EDGES / WARPS_CTA, NTHREADS>>>(emb, nidx, out);
}

// round 7
// speedup vs baseline: 3.7669x; 1.0463x over previous
#include <cuda_runtime.h>
#include <cuda_bf16.h>

#define EMBED_DIM   256
#define NUM_EDGES   16384
#define NTHREADS    128
#define WARPS_CTA   (NTHREADS / 32)

// g_offs[e] = lower_bound(seg, e); g_offs[NUM_EDGES] = total.
__device__ int g_offs[NUM_EDGES + 1];

// Diff-based boundary fill: no dependent load chains.
__global__ void bounds_kernel(const int* __restrict__ seg, int total)
{
    int i = blockIdx.x * blockDim.x + threadIdx.x;
    if (i >= total) return;
    int cur = seg[i];
    if (i == 0) {
        for (int e = 0; e <= cur; e++) g_offs[e] = 0;
    } else {
        int prev = seg[i - 1];
        for (int e = prev + 1; e <= cur; e++) g_offs[e] = i;
    }
    if (i == total - 1) {
        for (int e = cur + 1; e <= NUM_EDGES; e++) g_offs[e] = total;
    }
}

// 32-byte (8-float) gather with L2 evict_last (ptxas requires .v4.b64 for this hint).
__device__ __forceinline__ ulonglong4 ldg_el8(const ulonglong4* p)
{
    ulonglong4 v;
    asm volatile("ld.global.nc.L2::evict_last.v4.b64 {%0,%1,%2,%3}, [%4];"
                 : "=l"(v.x), "=l"(v.y), "=l"(v.z), "=l"(v.w)
                 : "l"(p));
    return v;
}

// Streaming index load (evict-first).
__device__ __forceinline__ int ldg_cs(const int* p)
{
    int v;
    asm volatile("ld.global.cs.b32 %0, [%1];" : "=r"(v) : "l"(p));
    return v;
}

// Streaming 32-byte store (evict-first: don't displace table lines in L2).
__device__ __forceinline__ void stg_cs8(ulonglong4* p, const ulonglong4 v)
{
    asm volatile("st.global.cs.v4.b64 [%0], {%1,%2,%3,%4};"
                 :: "l"(p), "l"(v.x), "l"(v.y), "l"(v.z), "l"(v.w));
}

__device__ __forceinline__ void accadd8(float* a, const ulonglong4 v)
{
    const float* f = (const float*)&v;
#pragma unroll
    for (int i = 0; i < 8; i++) a[i] += f[i];
}

// One WARP per hyperedge. Lane l owns the 32-byte chunk at byte offset 32*l of
// the 1024-byte row: one 256-bit load covers the whole row per member per warp.
// Index loads are software-pipelined one chunk ahead so the LDG queue never
// drains at chunk boundaries.
__global__ void __launch_bounds__(NTHREADS)
agg_kernel(const float* __restrict__ emb,   // [NUM_NODES, 256]
           const int*   __restrict__ nidx,  // [TOTAL]
           float*       __restrict__ out)   // [NUM_EDGES, 256]
{
    const int lane = threadIdx.x & 31;
    const int e    = blockIdx.x * WARPS_CTA + (threadIdx.x >> 5);

    const int lo = g_offs[e];
    const int hi = g_offs[e + 1];

    const ulonglong4* __restrict__ rows = (const ulonglong4*)emb;  // 32 chunks/row

    float acc[8];
#pragma unroll
    for (int i = 0; i < 8; i++) acc[i] = 0.0f;

    // Prefetch first index chunk.
    int myidx = 0;
    if (lo + lane < hi) myidx = ldg_cs(nidx + lo + lane);

    for (int base = lo; base < hi; base += 32) {
        const int cnt = min(32, hi - base);
        const int cur = myidx;

        // Prefetch NEXT chunk's indices before issuing this chunk's gathers.
        const int nb = base + 32;
        if (nb + lane < hi) myidx = ldg_cs(nidx + nb + lane);

        int j = 0;
        // 4 members per iteration -> 4 independent 32B gathers in flight per thread.
        for (; j + 3 < cnt; j += 4) {
            const int n0 = __shfl_sync(0xffffffffu, cur, j);
            const int n1 = __shfl_sync(0xffffffffu, cur, j + 1);
            const int n2 = __shfl_sync(0xffffffffu, cur, j + 2);
            const int n3 = __shfl_sync(0xffffffffu, cur, j + 3);
            ulonglong4 v0 = ldg_el8(rows + (size_t)n0 * 32 + lane);
            ulonglong4 v1 = ldg_el8(rows + (size_t)n1 * 32 + lane);
            ulonglong4 v2 = ldg_el8(rows + (size_t)n2 * 32 + lane);
            ulonglong4 v3 = ldg_el8(rows + (size_t)n3 * 32 + lane);
            accadd8(acc, v0);
            accadd8(acc, v1);
            accadd8(acc, v2);
            accadd8(acc, v3);
        }
        for (; j < cnt; j++) {
            const int n = __shfl_sync(0xffffffffu, cur, j);
            accadd8(acc, ldg_el8(rows + (size_t)n * 32 + lane));
        }
    }

    const int cnt = hi - lo;
    const float inv = 1.0f / (float)(cnt > 0 ? cnt : 1);
#pragma unroll
    for (int i = 0; i < 8; i++) acc[i] *= inv;

    ulonglong4 res;
    float* rf = (float*)&res;
#pragma unroll
    for (int i = 0; i < 8; i++) rf[i] = acc[i];

    stg_cs8((ulonglong4*)out + (size_t)e * 32 + lane, res);
}

extern "C" void kernel_launch(void* const* d_in, const int* in_sizes, int n_in,
                              void* d_out, int out_size)
{
    const float* emb  = (const float*)d_in[0];
    const int*   nidx = (const int*)d_in[1];
    const int*   seg  = (const int*)d_in[2];
    float*       out  = (float*)d_out;
    const int total = in_sizes[1];

    bounds_kernel<<<(total + 255) / 256, 256>>>(seg, total);
    agg_kernel<<<NUM_EDGES / WARPS_CTA, NTHREADS>>>(emb, nidx, out);
}